// round 1
// baseline (speedup 1.0000x reference)
#include <cuda_runtime.h>
#include <cuda_bf16.h>

// Problem constants (fixed by setup_inputs)
#define SEQ    4096
#define NHEAD  16
#define NBATCH 2
#define DK     128
#define DV     128
#define CH     64
#define NC     (SEQ / CH)              // 64 chunks per sequence
#define TOTC   (NBATCH * NHEAD * NC)   // 2048 chunk-tiles

// Scratch (static __device__ — no runtime allocation)
__device__ float g_U[TOTC * CH * DV];      // u = Tinv @ (v*beta)            [64][128]
__device__ float g_W[TOTC * CH * DK];      // kcd = Tinv @ (k*beta*e^gcs)    [64][128]
__device__ float g_ATT[TOTC * CH * CH];    // masked (q k^T)*decay           [64][64]
__device__ float g_QG[TOTC * CH * DK];     // q * e^gcs                      [64][128]
__device__ float g_KDT[TOTC * DK * CH];    // (k * e^{glast-gcs})^T          [128][64]
__device__ float g_EGL[TOTC];              // e^{g_last}

#define P1_SMEM_FLOATS (3*64*129 + 64*65 + 5*64)
#define P2_SMEM_FLOATS (128*32 + 8448 + 8448 + 64*68 + 64*36)
#define P1_SMEM (P1_SMEM_FLOATS * 4)
#define P2_SMEM (P2_SMEM_FLOATS * 4)

// ---------------------------------------------------------------------------
// Phase 1: per-chunk preprocessing. grid = 2048, block = 256.
// ---------------------------------------------------------------------------
__global__ __launch_bounds__(256, 1) void gdn_phase1(
    const float* __restrict__ qin, const float* __restrict__ kin,
    const float* __restrict__ vin, const float* __restrict__ gin,
    const float* __restrict__ bin)
{
    extern __shared__ float sm[];
    float* q_sh  = sm;                  // [64][129] normalized q * Dk^-0.5
    float* k_sh  = q_sh + 64 * 129;     // [64][129] normalized k
    float* v_sh  = k_sh + 64 * 129;     // [64][129] v * beta
    float* A_sh  = v_sh + 64 * 129;     // [64][65]  strict-lower system matrix
    float* gcs   = A_sh + 64 * 65;      // [64] cum log-decay
    float* betaS = gcs + 64;            // [64]
    float* bgS   = betaS + 64;          // [64] beta * e^gcs
    float* edec  = bgS + 64;            // [64] e^{glast - gcs}
    float* egcs  = edec + 64;           // [64] e^{gcs}

    const int cid = blockIdx.x;
    const int n   = cid & (NC - 1);
    const int bh  = cid / NC;
    const int h   = bh & (NHEAD - 1);
    const int b   = bh / NHEAD;
    const int tid = threadIdx.x;
    const int s0  = n * CH;

    if (tid < CH) {
        int idx = (b * SEQ + s0 + tid) * NHEAD + h;
        gcs[tid]   = gin[idx];
        betaS[tid] = bin[idx];
    }
    __syncthreads();
    if (tid == 0) {
        float run = 0.f;
        #pragma unroll
        for (int i = 0; i < CH; i++) { run += gcs[i]; gcs[i] = run; }
    }
    __syncthreads();
    if (tid < CH) {
        float gl = gcs[CH - 1];
        float e  = __expf(gcs[tid]);
        egcs[tid] = e;
        bgS[tid]  = betaS[tid] * e;
        edec[tid] = __expf(gl - gcs[tid]);
    }

    // Load + l2-normalize q and k (one warp handles 8 rows)
    {
        const int w = tid >> 5, lane = tid & 31;
        #pragma unroll
        for (int r = 0; r < 8; r++) {
            const int i = w * 8 + r;
            const int base = ((b * SEQ + s0 + i) * NHEAD + h) * DK;
            float k0 = kin[base + lane],      k1 = kin[base + lane + 32];
            float k2 = kin[base + lane + 64], k3 = kin[base + lane + 96];
            float ss = k0*k0 + k1*k1 + k2*k2 + k3*k3;
            #pragma unroll
            for (int o = 16; o; o >>= 1) ss += __shfl_xor_sync(0xffffffffu, ss, o);
            float rn = rsqrtf(ss + 1e-6f);
            k_sh[i*129 + lane]      = k0 * rn; k_sh[i*129 + lane + 32] = k1 * rn;
            k_sh[i*129 + lane + 64] = k2 * rn; k_sh[i*129 + lane + 96] = k3 * rn;

            float q0 = qin[base + lane],      q1 = qin[base + lane + 32];
            float q2 = qin[base + lane + 64], q3 = qin[base + lane + 96];
            float sq = q0*q0 + q1*q1 + q2*q2 + q3*q3;
            #pragma unroll
            for (int o = 16; o; o >>= 1) sq += __shfl_xor_sync(0xffffffffu, sq, o);
            float rq = rsqrtf(sq + 1e-6f) * 0.08838834764831843f; // * Dk^-0.5
            q_sh[i*129 + lane]      = q0 * rq; q_sh[i*129 + lane + 32] = q1 * rq;
            q_sh[i*129 + lane + 64] = q2 * rq; q_sh[i*129 + lane + 96] = q3 * rq;
        }
    }
    // v * beta
    for (int e = tid; e < CH * DV; e += 256) {
        int i = e >> 7, d = e & 127;
        v_sh[i*129 + d] = vin[((b * SEQ + s0 + i) * NHEAD + h) * DV + d] * betaS[i];
    }
    __syncthreads();

    // A (to shared, strict lower) and attn (to global, incl diag): 4x4 tiles
    {
        const int ti = tid >> 4, tj = tid & 15;
        const int i0 = ti * 4, j0 = tj * 4;
        float* dstA = g_ATT + cid * (CH * CH);
        if (tj <= ti) {
            float ak[4][4], aq[4][4];
            #pragma unroll
            for (int a = 0; a < 4; a++)
                #pragma unroll
                for (int c2 = 0; c2 < 4; c2++) { ak[a][c2] = 0.f; aq[a][c2] = 0.f; }
            #pragma unroll 4
            for (int d = 0; d < DK; d++) {
                float kj[4], ki[4], qi[4];
                #pragma unroll
                for (int x = 0; x < 4; x++) {
                    kj[x] = k_sh[(j0 + x) * 129 + d];
                    ki[x] = k_sh[(i0 + x) * 129 + d];
                    qi[x] = q_sh[(i0 + x) * 129 + d];
                }
                #pragma unroll
                for (int a = 0; a < 4; a++)
                    #pragma unroll
                    for (int c2 = 0; c2 < 4; c2++) {
                        ak[a][c2] += ki[a] * kj[c2];
                        aq[a][c2] += qi[a] * kj[c2];
                    }
            }
            #pragma unroll
            for (int a = 0; a < 4; a++) {
                int i = i0 + a;
                #pragma unroll
                for (int c2 = 0; c2 < 4; c2++) {
                    int j = j0 + c2;
                    float dec = __expf(gcs[i] - gcs[j]);
                    A_sh[i*65 + j] = (i > j)  ? betaS[i] * dec * ak[a][c2] : 0.f;
                    dstA[i*64 + j] = (i >= j) ? dec * aq[a][c2]            : 0.f;
                }
            }
        } else {
            #pragma unroll
            for (int a = 0; a < 4; a++)
                #pragma unroll
                for (int c2 = 0; c2 < 4; c2++) {
                    A_sh[(i0 + a) * 65 + j0 + c2] = 0.f;
                    dstA[(i0 + a) * 64 + j0 + c2] = 0.f;
                }
        }
    }
    __syncthreads();

    // Forward substitution (I + A) x = rhs; 256 columns:
    //   tid <  128 -> u column  (rhs = v*beta)
    //   tid >= 128 -> kcd column (rhs = k * beta * e^gcs)
    {
        const int  col = tid & 127;
        const bool isU = tid < 128;
        float x[CH];
        #pragma unroll
        for (int i = 0; i < CH; i++) {
            float acc = isU ? v_sh[i*129 + col] : k_sh[i*129 + col] * bgS[i];
            #pragma unroll
            for (int j = 0; j < i; j++) acc -= A_sh[i*65 + j] * x[j];
            x[i] = acc;
        }
        float* dst = (isU ? g_U : g_W) + cid * (CH * DK) + col;
        #pragma unroll
        for (int i = 0; i < CH; i++) dst[i * 128] = x[i];
    }

    // qg = q * e^gcs ; kdT = (k * e^{glast-gcs}) transposed
    for (int e = tid; e < CH * DK; e += 256) {
        int i = e >> 7, d = e & 127;
        g_QG[cid * (CH * DK) + e] = q_sh[i*129 + d] * egcs[i];
    }
    for (int e = tid; e < DK * CH; e += 256) {
        int d = e >> 6, i = e & 63;
        g_KDT[cid * (DK * CH) + e] = k_sh[i*129 + d] * edec[i];
    }
    if (tid == 0) g_EGL[cid] = __expf(gcs[CH - 1]);
}

// ---------------------------------------------------------------------------
// Phase 2: sequential chunk scan. grid = 32 heads * 4 Dv-slices = 128 CTAs.
// State slice S[128][32] lives in shared; register-tiled matmuls.
// ---------------------------------------------------------------------------
__global__ __launch_bounds__(256, 1) void gdn_phase2(float* __restrict__ out)
{
    extern __shared__ float sm[];
    float* S_sh = sm;                   // [128][32]
    float* bufA = S_sh + 128 * 32;      // w as [64][132] / kdT as [128][66]
    float* bufB = bufA + 8448;          // qg as [64][132]
    float* att  = bufB + 8448;          // [64][68]
    float* vnw  = att + 64 * 68;        // [64][36]

    const int bh    = blockIdx.x >> 2;
    const int slice = blockIdx.x & 3;
    const int h     = bh & (NHEAD - 1);
    const int b     = bh / NHEAD;
    const int tid   = threadIdx.x;
    const int tc    = tid & 7;          // 8 column-groups of 4
    const int tr    = tid >> 3;         // 32 row threads
    const int c0    = tc * 4;
    const int vb0   = slice * 32;

    for (int e = tid; e < 4096; e += 256) S_sh[e] = 0.f;
    __syncthreads();

    for (int n = 0; n < NC; n++) {
        const int cid = bh * NC + n;
        const float* Wp = g_W   + cid * 8192;
        const float* Qp = g_QG  + cid * 8192;
        const float* Ap = g_ATT + cid * 4096;
        const float* Up = g_U   + cid * 8192;
        const float* Kp = g_KDT + cid * 8192;

        // stage w, qg, attn
        for (int e = tid; e < 8192; e += 256) {
            int i = e >> 7, d = e & 127;
            bufA[i*132 + d] = Wp[e];
            bufB[i*132 + d] = Qp[e];
        }
        for (int e = tid; e < 4096; e += 256) {
            int i = e >> 6, j = e & 63;
            att[i*68 + j] = Ap[e];
        }
        __syncthreads();

        // v_new = u - w @ S   and   oa = qg @ S   (fused over K=128)
        float vn[2][4], oa[2][4];
        #pragma unroll
        for (int m = 0; m < 2; m++) {
            const float4 u4 = *(const float4*)(Up + (tr + 32*m) * 128 + vb0 + c0);
            vn[m][0] = u4.x; vn[m][1] = u4.y; vn[m][2] = u4.z; vn[m][3] = u4.w;
            oa[m][0] = 0.f; oa[m][1] = 0.f; oa[m][2] = 0.f; oa[m][3] = 0.f;
        }
        #pragma unroll 4
        for (int kk = 0; kk < 128; kk++) {
            float4 s4 = *(const float4*)&S_sh[kk * 32 + c0];
            float w0 = bufA[tr*132 + kk], w1 = bufA[(tr + 32)*132 + kk];
            float p0 = bufB[tr*132 + kk], p1 = bufB[(tr + 32)*132 + kk];
            vn[0][0] -= w0 * s4.x; vn[0][1] -= w0 * s4.y; vn[0][2] -= w0 * s4.z; vn[0][3] -= w0 * s4.w;
            vn[1][0] -= w1 * s4.x; vn[1][1] -= w1 * s4.y; vn[1][2] -= w1 * s4.z; vn[1][3] -= w1 * s4.w;
            oa[0][0] += p0 * s4.x; oa[0][1] += p0 * s4.y; oa[0][2] += p0 * s4.z; oa[0][3] += p0 * s4.w;
            oa[1][0] += p1 * s4.x; oa[1][1] += p1 * s4.y; oa[1][2] += p1 * s4.z; oa[1][3] += p1 * s4.w;
        }
        #pragma unroll
        for (int m = 0; m < 2; m++) {
            float4 t; t.x = vn[m][0]; t.y = vn[m][1]; t.z = vn[m][2]; t.w = vn[m][3];
            *(float4*)&vnw[(tr + 32*m) * 36 + c0] = t;
        }
        __syncthreads();

        // oa += attn @ v_new ; write output
        #pragma unroll 4
        for (int j = 0; j < 64; j++) {
            float4 v4 = *(const float4*)&vnw[j * 36 + c0];
            float a0 = att[tr*68 + j], a1 = att[(tr + 32)*68 + j];
            oa[0][0] += a0 * v4.x; oa[0][1] += a0 * v4.y; oa[0][2] += a0 * v4.z; oa[0][3] += a0 * v4.w;
            oa[1][0] += a1 * v4.x; oa[1][1] += a1 * v4.y; oa[1][2] += a1 * v4.z; oa[1][3] += a1 * v4.w;
        }
        #pragma unroll
        for (int m = 0; m < 2; m++) {
            int i = tr + 32 * m;
            float4 t; t.x = oa[m][0]; t.y = oa[m][1]; t.z = oa[m][2]; t.w = oa[m][3];
            *(float4*)(out + ((b * SEQ + n * CH + i) * NHEAD + h) * DV + vb0 + c0) = t;
        }

        // stage kdT (bufA free since the sync after the K-loop)
        for (int e = tid; e < 8192; e += 256) {
            int d = e >> 6, i = e & 63;
            bufA[d*66 + i] = Kp[e];
        }
        __syncthreads();

        // S = S * e^{g_last} + kdT @ v_new
        const float egl = g_EGL[cid];
        float sa[4][4];
        #pragma unroll
        for (int m = 0; m < 4; m++) { sa[m][0] = 0.f; sa[m][1] = 0.f; sa[m][2] = 0.f; sa[m][3] = 0.f; }
        #pragma unroll 2
        for (int i2 = 0; i2 < 64; i2++) {
            float4 v4 = *(const float4*)&vnw[i2 * 36 + c0];
            float a0 = bufA[tr*66 + i2],        a1 = bufA[(tr + 32)*66 + i2];
            float a2 = bufA[(tr + 64)*66 + i2], a3 = bufA[(tr + 96)*66 + i2];
            sa[0][0] += a0 * v4.x; sa[0][1] += a0 * v4.y; sa[0][2] += a0 * v4.z; sa[0][3] += a0 * v4.w;
            sa[1][0] += a1 * v4.x; sa[1][1] += a1 * v4.y; sa[1][2] += a1 * v4.z; sa[1][3] += a1 * v4.w;
            sa[2][0] += a2 * v4.x; sa[2][1] += a2 * v4.y; sa[2][2] += a2 * v4.z; sa[2][3] += a2 * v4.w;
            sa[3][0] += a3 * v4.x; sa[3][1] += a3 * v4.y; sa[3][2] += a3 * v4.z; sa[3][3] += a3 * v4.w;
        }
        #pragma unroll
        for (int m = 0; m < 4; m++) {
            float4* sp = (float4*)&S_sh[(tr + 32*m) * 32 + c0];
            float4 s = *sp;
            s.x = s.x * egl + sa[m][0]; s.y = s.y * egl + sa[m][1];
            s.z = s.z * egl + sa[m][2]; s.w = s.w * egl + sa[m][3];
            *sp = s;
        }
        __syncthreads();
    }
}

// ---------------------------------------------------------------------------
extern "C" void kernel_launch(void* const* d_in, const int* in_sizes, int n_in,
                              void* d_out, int out_size) {
    (void)in_sizes; (void)n_in; (void)out_size;
    const float* q    = (const float*)d_in[0];
    const float* k    = (const float*)d_in[1];
    const float* v    = (const float*)d_in[2];
    const float* g    = (const float*)d_in[3];
    const float* beta = (const float*)d_in[4];
    float* out = (float*)d_out;

    cudaFuncSetAttribute(gdn_phase1, cudaFuncAttributeMaxDynamicSharedMemorySize, P1_SMEM);
    cudaFuncSetAttribute(gdn_phase2, cudaFuncAttributeMaxDynamicSharedMemorySize, P2_SMEM);

    gdn_phase1<<<TOTC, 256, P1_SMEM>>>(q, k, v, g, beta);
    gdn_phase2<<<NBATCH * NHEAD * 4, 256, P2_SMEM>>>(out);
}

// round 4
// speedup vs baseline: 1.8776x; 1.8776x over previous
#include <cuda_runtime.h>
#include <cuda_bf16.h>

// Problem constants (fixed by setup_inputs)
#define SEQ    4096
#define NHEAD  16
#define NBATCH 2
#define DK     128
#define DV     128
#define CH     64
#define NC     (SEQ / CH)
#define TOTC   (NBATCH * NHEAD * NC)   // 2048 chunk-tiles

typedef unsigned long long u64t;

// packed f32x2 helpers (sm_100+ FFMA2 path)
__device__ __forceinline__ u64t pk2(float v) {
    u64t r; asm("mov.b64 %0,{%1,%1};" : "=l"(r) : "f"(v)); return r;
}
__device__ __forceinline__ void fmaA(u64t& d, u64t a, u64t b) {
    asm("fma.rn.f32x2 %0,%1,%2,%0;" : "+l"(d) : "l"(a), "l"(b));
}
__device__ __forceinline__ u64t fma3(u64t a, u64t b, u64t c) {
    u64t d; asm("fma.rn.f32x2 %0,%1,%2,%3;" : "=l"(d) : "l"(a), "l"(b), "l"(c)); return d;
}
__device__ __forceinline__ float2 up2(u64t a) {
    float2 r; asm("mov.b64 {%0,%1},%2;" : "=f"(r.x), "=f"(r.y) : "l"(a)); return r;
}
__device__ __forceinline__ void cpa16(unsigned dst, const void* src) {
    asm volatile("cp.async.cg.shared.global [%0],[%1],16;" :: "r"(dst), "l"(src) : "memory");
}
#define CP_COMMIT asm volatile("cp.async.commit_group;" ::: "memory")
#define CP_WAIT0  asm volatile("cp.async.wait_group 0;" ::: "memory")

// Scratch (static __device__ — no runtime allocation)
__device__ __align__(16) float g_U[TOTC * CH * DV];    // u               [64][128] row-major
__device__ __align__(16) float g_W[TOTC * CH * DK];    // kcd             [64][128] row-major
__device__ __align__(16) float g_ATT[TOTC * CH * CH];  // masked attn     [64][64]
__device__ __align__(16) float g_QG[TOTC * CH * DK];   // q*e^gcs         [64][128]
__device__ __align__(16) float g_KDT[TOTC * DK * CH];  // (k*e^{gl-g})^T  [128][64]
__device__ float g_EGL[TOTC];

// Phase-1 smem layout (floats)
#define P1_Q   0
#define P1_K   8448
#define P1_V   16896
#define P1_A   25344          // [64][68]
#define P1_VEC 29696          // 6 x 64
#define P1_SMEM ((30080) * 4)

// Phase-2 smem layout (floats)
#define SO_S   0              // [128][32]
#define SO_W   4096           // [64][132]
#define SO_P   12544          // [64][132]
#define SO_A   20992          // [64][72]
#define SO_K   25600          // [128][68]
#define SO_V   34304          // [64][36]
#define P2_SMEM ((36608) * 4)

// ---------------------------------------------------------------------------
// Phase 1: per-chunk preprocessing. grid = 2048, block = 256.
// ---------------------------------------------------------------------------
__global__ __launch_bounds__(256, 1) void gdn_phase1(
    const float* __restrict__ qin, const float* __restrict__ kin,
    const float* __restrict__ vin, const float* __restrict__ gin,
    const float* __restrict__ bin)
{
    extern __shared__ float sm[];
    float* q_sh  = sm + P1_Q;        // [64][132]
    float* k_sh  = sm + P1_K;        // [64][132]
    float* v_sh  = sm + P1_V;        // [64][132]
    float* A_sh  = sm + P1_A;        // [64][68]
    float* gcs   = sm + P1_VEC;      // [64]
    float* betaS = gcs + 64;
    float* bgS   = betaS + 64;
    float* edec  = bgS + 64;
    float* egcs  = edec + 64;
    float* iegcs = egcs + 64;

    const int cid = blockIdx.x;
    const int n   = cid & (NC - 1);
    const int bh  = cid / NC;
    const int h   = bh & (NHEAD - 1);
    const int b   = bh / NHEAD;
    const int tid = threadIdx.x;
    const int s0  = n * CH;

    if (tid < CH) {
        int idx = (b * SEQ + s0 + tid) * NHEAD + h;
        gcs[tid]   = gin[idx];
        betaS[tid] = bin[idx];
    }
    __syncthreads();
    if (tid == 0) {
        float run = 0.f;
        #pragma unroll
        for (int i = 0; i < CH; i++) { run += gcs[i]; gcs[i] = run; }
    }
    __syncthreads();
    if (tid < CH) {
        float e  = __expf(gcs[tid]);
        egcs[tid]  = e;
        iegcs[tid] = 1.0f / e;
        bgS[tid]   = betaS[tid] * e;
    }
    __syncthreads();
    if (tid < CH) edec[tid] = egcs[CH - 1] * iegcs[tid];

    // Load + l2-normalize q and k (one warp per 8 rows)
    {
        const int w = tid >> 5, lane = tid & 31;
        #pragma unroll
        for (int r = 0; r < 8; r++) {
            const int i = w * 8 + r;
            const int base = ((b * SEQ + s0 + i) * NHEAD + h) * DK;
            float k0 = kin[base + lane],      k1 = kin[base + lane + 32];
            float k2 = kin[base + lane + 64], k3 = kin[base + lane + 96];
            float ss = k0*k0 + k1*k1 + k2*k2 + k3*k3;
            #pragma unroll
            for (int o = 16; o; o >>= 1) ss += __shfl_xor_sync(0xffffffffu, ss, o);
            float rn = rsqrtf(ss + 1e-6f);
            k_sh[i*132 + lane]      = k0 * rn; k_sh[i*132 + lane + 32] = k1 * rn;
            k_sh[i*132 + lane + 64] = k2 * rn; k_sh[i*132 + lane + 96] = k3 * rn;

            float q0 = qin[base + lane],      q1 = qin[base + lane + 32];
            float q2 = qin[base + lane + 64], q3 = qin[base + lane + 96];
            float sq = q0*q0 + q1*q1 + q2*q2 + q3*q3;
            #pragma unroll
            for (int o = 16; o; o >>= 1) sq += __shfl_xor_sync(0xffffffffu, sq, o);
            float rq = rsqrtf(sq + 1e-6f) * 0.08838834764831843f;
            q_sh[i*132 + lane]      = q0 * rq; q_sh[i*132 + lane + 32] = q1 * rq;
            q_sh[i*132 + lane + 64] = q2 * rq; q_sh[i*132 + lane + 96] = q3 * rq;
        }
    }
    // v * beta, vectorized
    {
        #pragma unroll
        for (int r = 0; r < 8; r++) {
            int e4 = tid + 256 * r;                // 0..2047
            int i = e4 >> 5, d4 = e4 & 31;
            float4 vv = *(const float4*)(vin + ((b * SEQ + s0 + i) * NHEAD + h) * DV + 4 * d4);
            float bb = betaS[i];
            vv.x *= bb; vv.y *= bb; vv.z *= bb; vv.w *= bb;
            *(float4*)&v_sh[i*132 + 4*d4] = vv;
        }
    }
    __syncthreads();

    // Full 64x64 GEMM (strided 4x4 tiles), packed over d:
    //   ak = (k beta-side) k^T ,  aq = q k^T
    {
        const int ti = tid >> 4, tj = tid & 15;
        u64t ak[4][4], aq[4][4];
        #pragma unroll
        for (int a = 0; a < 4; a++)
            #pragma unroll
            for (int c = 0; c < 4; c++) { ak[a][c] = 0ull; aq[a][c] = 0ull; }

        for (int d = 0; d < DK; d += 4) {
            ulonglong2 kj[4], ki[4], qi[4];
            #pragma unroll
            for (int c = 0; c < 4; c++)
                kj[c] = *(const ulonglong2*)&k_sh[(tj + 16*c)*132 + d];
            #pragma unroll
            for (int a = 0; a < 4; a++) {
                ki[a] = *(const ulonglong2*)&k_sh[(ti + 16*a)*132 + d];
                qi[a] = *(const ulonglong2*)&q_sh[(ti + 16*a)*132 + d];
            }
            #pragma unroll
            for (int a = 0; a < 4; a++)
                #pragma unroll
                for (int c = 0; c < 4; c++) {
                    fmaA(ak[a][c], ki[a].x, kj[c].x);
                    fmaA(ak[a][c], ki[a].y, kj[c].y);
                    fmaA(aq[a][c], qi[a].x, kj[c].x);
                    fmaA(aq[a][c], qi[a].y, kj[c].y);
                }
        }
        float* dstA = g_ATT + cid * (CH * CH);
        float eg_i[4], be_i[4], ie_j[4];
        #pragma unroll
        for (int a = 0; a < 4; a++) {
            int i = ti + 16*a;
            eg_i[a] = egcs[i]; be_i[a] = betaS[i];
        }
        #pragma unroll
        for (int c = 0; c < 4; c++) {
            int j = tj + 16*c;
            ie_j[c] = iegcs[j];
        }
        #pragma unroll
        for (int a = 0; a < 4; a++) {
            int i = ti + 16*a;
            #pragma unroll
            for (int c = 0; c < 4; c++) {
                int j = tj + 16*c;
                float2 tk = up2(ak[a][c]);
                float2 tq = up2(aq[a][c]);
                float sk = tk.x + tk.y, sq = tq.x + tq.y;
                float dec = eg_i[a] * ie_j[c];
                A_sh[i*68 + j] = (i > j)  ? be_i[a] * dec * sk : 0.f;
                dstA[i*64 + j] = (i >= j) ? dec * sq           : 0.f;
            }
        }
    }
    __syncthreads();

    // Forward substitution (I + A) x = rhs; 256 columns (128 U + 128 W)
    {
        const int  col = tid & 127;
        const bool isU = tid < 128;
        float x[CH];
        #pragma unroll
        for (int i = 0; i < CH; i++) x[i] = 0.f;
        #pragma unroll
        for (int i = 0; i < CH; i++) {
            float acc = isU ? v_sh[i*132 + col] : k_sh[i*132 + col] * bgS[i];
            const int nb = (i + 3) >> 2;
            #pragma unroll
            for (int j4 = 0; j4 < nb; j4++) {
                float4 a4 = *(const float4*)&A_sh[i*68 + 4*j4];
                acc -= a4.x * x[4*j4] + a4.y * x[4*j4+1] + a4.z * x[4*j4+2] + a4.w * x[4*j4+3];
            }
            x[i] = acc;
        }
        float* dst = (isU ? g_U : g_W) + cid * (CH * DK) + col;
        #pragma unroll
        for (int i = 0; i < CH; i++) dst[i * 128] = x[i];
    }

    // qg = q * e^gcs (vectorized); kdT = (k * e^{glast-g})^T
    {
        #pragma unroll
        for (int r = 0; r < 8; r++) {
            int e4 = tid + 256 * r;
            int i = e4 >> 5, d4 = e4 & 31;
            float4 qq = *(const float4*)&q_sh[i*132 + 4*d4];
            float e = egcs[i];
            qq.x *= e; qq.y *= e; qq.z *= e; qq.w *= e;
            *(float4*)(g_QG + cid * (CH*DK) + e4 * 4) = qq;
        }
    }
    for (int e = tid; e < DK * CH; e += 256) {
        int d = e >> 6, i = e & 63;
        g_KDT[cid * (DK * CH) + e] = k_sh[i*132 + d] * edec[i];
    }
    if (tid == 0) g_EGL[cid] = egcs[CH - 1];
}

// ---------------------------------------------------------------------------
// Phase 2: sequential chunk scan. grid = 32 bh * 4 Dv-slices = 128 CTAs.
// Packed f32x2 math, float4 shared loads, cp.async staging.
// ---------------------------------------------------------------------------
__global__ __launch_bounds__(256, 1) void gdn_phase2(float* __restrict__ out)
{
    extern __shared__ float sm[];
    float* S_sh = sm + SO_S;     // [128][32]
    float* bufW = sm + SO_W;     // [64][132]
    float* bufP = sm + SO_P;     // [64][132]
    float* attS = sm + SO_A;     // [64][72]
    float* kdS  = sm + SO_K;     // [128][68]
    float* vnw  = sm + SO_V;     // [64][36]
    const unsigned sbase = (unsigned)__cvta_generic_to_shared(sm);

    const int bh    = blockIdx.x >> 2;
    const int slice = blockIdx.x & 3;
    const int h     = bh & (NHEAD - 1);
    const int b     = bh / NHEAD;
    const int tid   = threadIdx.x;
    const int tc    = tid & 7;
    const int tr    = tid >> 3;          // 0..31
    const int c0    = tc * 4;
    const int vb0   = slice * 32;

    for (int e = tid; e < 4096; e += 256) S_sh[e] = 0.f;
    __syncthreads();

    for (int n = 0; n < NC; n++) {
        const int cid = bh * NC + n;
        const float* Wp = g_W   + cid * 8192;
        const float* Qp = g_QG  + cid * 8192;
        const float* Ap = g_ATT + cid * 4096;
        const float* Up = g_U   + cid * 8192;
        const float* Kp = g_KDT + cid * 8192;

        // stage W, P(=qg), att via cp.async
        #pragma unroll
        for (int r = 0; r < 8; r++) {
            int g = tid + 256 * r;               // 0..2047 float4s
            int i = g >> 5, d4 = g & 31;
            unsigned doff = (unsigned)((SO_W + i*132 + 4*d4) * 4);
            cpa16(sbase + doff, Wp + g * 4);
            unsigned poff = (unsigned)((SO_P + i*132 + 4*d4) * 4);
            cpa16(sbase + poff, Qp + g * 4);
        }
        #pragma unroll
        for (int r = 0; r < 4; r++) {
            int g = tid + 256 * r;               // 0..1023 float4s
            int i = g >> 4, j4 = g & 15;
            cpa16(sbase + (unsigned)((SO_A + i*72 + 4*j4) * 4), Ap + g * 4);
        }
        CP_COMMIT;

        // prefetch u rows + egl while cp.async lands
        const float4 u0v = *(const float4*)(Up + tr * 128 + vb0 + c0);
        const float4 u1v = *(const float4*)(Up + (tr + 32) * 128 + vb0 + c0);
        const float egl = g_EGL[cid];

        CP_WAIT0;
        __syncthreads();

        // loop1: acc = W@S (rows tr,tr+32) and oa = qg@S, packed
        u64t vna0 = 0, vnb0 = 0, vna1 = 0, vnb1 = 0;
        u64t oa0 = 0, ob0 = 0, oa1 = 0, ob1 = 0;
        for (int kk = 0; kk < 128; kk += 4) {
            float4 w0v = *(const float4*)&bufW[tr*132 + kk];
            float4 w1v = *(const float4*)&bufW[(tr+32)*132 + kk];
            float4 p0v = *(const float4*)&bufP[tr*132 + kk];
            float4 p1v = *(const float4*)&bufP[(tr+32)*132 + kk];
            #pragma unroll
            for (int u = 0; u < 4; u++) {
                ulonglong2 s = *(const ulonglong2*)&S_sh[(kk+u)*32 + c0];
                u64t w0 = pk2(((const float*)&w0v)[u]);
                u64t w1 = pk2(((const float*)&w1v)[u]);
                u64t p0 = pk2(((const float*)&p0v)[u]);
                u64t p1 = pk2(((const float*)&p1v)[u]);
                fmaA(vna0, w0, s.x); fmaA(vnb0, w0, s.y);
                fmaA(vna1, w1, s.x); fmaA(vnb1, w1, s.y);
                fmaA(oa0,  p0, s.x); fmaA(ob0,  p0, s.y);
                fmaA(oa1,  p1, s.x); fmaA(ob1,  p1, s.y);
            }
        }
        {
            float2 a0 = up2(vna0), b0 = up2(vnb0), a1 = up2(vna1), b1 = up2(vnb1);
            float4 t0; t0.x = u0v.x - a0.x; t0.y = u0v.y - a0.y; t0.z = u0v.z - b0.x; t0.w = u0v.w - b0.y;
            float4 t1; t1.x = u1v.x - a1.x; t1.y = u1v.y - a1.y; t1.z = u1v.z - b1.x; t1.w = u1v.w - b1.y;
            *(float4*)&vnw[tr*36 + c0] = t0;
            *(float4*)&vnw[(tr+32)*36 + c0] = t1;
        }
        __syncthreads();

        // stage kdT now; its latency hides under loop2
        #pragma unroll
        for (int r = 0; r < 8; r++) {
            int g = tid + 256 * r;               // 0..2047 float4s
            int d = g >> 4, i4 = g & 15;
            cpa16(sbase + (unsigned)((SO_K + d*68 + 4*i4) * 4), Kp + g * 4);
        }
        CP_COMMIT;

        // loop2: oa += att @ v_new
        for (int j = 0; j < 64; j += 4) {
            float4 a0v = *(const float4*)&attS[tr*72 + j];
            float4 a1v = *(const float4*)&attS[(tr+32)*72 + j];
            #pragma unroll
            for (int u = 0; u < 4; u++) {
                ulonglong2 v = *(const ulonglong2*)&vnw[(j+u)*36 + c0];
                u64t a0 = pk2(((const float*)&a0v)[u]);
                u64t a1 = pk2(((const float*)&a1v)[u]);
                fmaA(oa0, a0, v.x); fmaA(ob0, a0, v.y);
                fmaA(oa1, a1, v.x); fmaA(ob1, a1, v.y);
            }
        }
        {
            float2 x0 = up2(oa0), y0 = up2(ob0), x1 = up2(oa1), y1 = up2(ob1);
            float4 t0; t0.x = x0.x; t0.y = x0.y; t0.z = y0.x; t0.w = y0.y;
            float4 t1; t1.x = x1.x; t1.y = x1.y; t1.z = y1.x; t1.w = y1.y;
            *(float4*)(out + ((b * SEQ + n * CH + tr) * NHEAD + h) * DV + vb0 + c0) = t0;
            *(float4*)(out + ((b * SEQ + n * CH + tr + 32) * NHEAD + h) * DV + vb0 + c0) = t1;
        }

        CP_WAIT0;
        __syncthreads();

        // loop3: S = S*egl + kdT @ v_new   (4 rows per thread)
        u64t s0a = 0, s0b = 0, s1a = 0, s1b = 0, s2a = 0, s2b = 0, s3a = 0, s3b = 0;
        for (int i2 = 0; i2 < 64; i2 += 4) {
            float4 k0v = *(const float4*)&kdS[tr*68 + i2];
            float4 k1v = *(const float4*)&kdS[(tr+32)*68 + i2];
            float4 k2v = *(const float4*)&kdS[(tr+64)*68 + i2];
            float4 k3v = *(const float4*)&kdS[(tr+96)*68 + i2];
            #pragma unroll
            for (int u = 0; u < 4; u++) {
                ulonglong2 v = *(const ulonglong2*)&vnw[(i2+u)*36 + c0];
                u64t a0 = pk2(((const float*)&k0v)[u]);
                u64t a1 = pk2(((const float*)&k1v)[u]);
                u64t a2 = pk2(((const float*)&k2v)[u]);
                u64t a3 = pk2(((const float*)&k3v)[u]);
                fmaA(s0a, a0, v.x); fmaA(s0b, a0, v.y);
                fmaA(s1a, a1, v.x); fmaA(s1b, a1, v.y);
                fmaA(s2a, a2, v.x); fmaA(s2b, a2, v.y);
                fmaA(s3a, a3, v.x); fmaA(s3b, a3, v.y);
            }
        }
        {
            const u64t eglp = pk2(egl);
            ulonglong2* sp0 = (ulonglong2*)&S_sh[tr*32 + c0];
            ulonglong2* sp1 = (ulonglong2*)&S_sh[(tr+32)*32 + c0];
            ulonglong2* sp2 = (ulonglong2*)&S_sh[(tr+64)*32 + c0];
            ulonglong2* sp3 = (ulonglong2*)&S_sh[(tr+96)*32 + c0];
            ulonglong2 s0 = *sp0, s1 = *sp1, s2 = *sp2, s3 = *sp3;
            s0.x = fma3(s0.x, eglp, s0a); s0.y = fma3(s0.y, eglp, s0b);
            s1.x = fma3(s1.x, eglp, s1a); s1.y = fma3(s1.y, eglp, s1b);
            s2.x = fma3(s2.x, eglp, s2a); s2.y = fma3(s2.y, eglp, s2b);
            s3.x = fma3(s3.x, eglp, s3a); s3.y = fma3(s3.y, eglp, s3b);
            *sp0 = s0; *sp1 = s1; *sp2 = s2; *sp3 = s3;
        }
        __syncthreads();
    }
}

// ---------------------------------------------------------------------------
extern "C" void kernel_launch(void* const* d_in, const int* in_sizes, int n_in,
                              void* d_out, int out_size) {
    (void)in_sizes; (void)n_in; (void)out_size;
    const float* q    = (const float*)d_in[0];
    const float* k    = (const float*)d_in[1];
    const float* v    = (const float*)d_in[2];
    const float* g    = (const float*)d_in[3];
    const float* beta = (const float*)d_in[4];
    float* out = (float*)d_out;

    cudaFuncSetAttribute(gdn_phase1, cudaFuncAttributeMaxDynamicSharedMemorySize, P1_SMEM);
    cudaFuncSetAttribute(gdn_phase2, cudaFuncAttributeMaxDynamicSharedMemorySize, P2_SMEM);

    gdn_phase1<<<TOTC, 256, P1_SMEM>>>(q, k, v, g, beta);
    gdn_phase2<<<NBATCH * NHEAD * 4, 256, P2_SMEM>>>(out);
}

// round 6
// speedup vs baseline: 1.9088x; 1.0166x over previous
#include <cuda_runtime.h>
#include <cuda_bf16.h>

// Problem constants (fixed by setup_inputs)
#define SEQ    4096
#define NHEAD  16
#define NBATCH 2
#define DK     128
#define DV     128
#define CH     64
#define NC     (SEQ / CH)
#define TOTC   (NBATCH * NHEAD * NC)   // 2048 chunk-tiles

typedef unsigned long long u64t;

// packed f32x2 helpers (sm_100+ FFMA2 path)
__device__ __forceinline__ void fmaA(u64t& d, u64t a, u64t b) {
    asm("fma.rn.f32x2 %0,%1,%2,%0;" : "+l"(d) : "l"(a), "l"(b));
}
__device__ __forceinline__ float2 up2(u64t a) {
    float2 r; asm("mov.b64 {%0,%1},%2;" : "=f"(r.x), "=f"(r.y) : "l"(a)); return r;
}
__device__ __forceinline__ void cpa16(unsigned dst, const void* src) {
    asm volatile("cp.async.cg.shared.global [%0],[%1],16;" :: "r"(dst), "l"(src) : "memory");
}
#define CP_COMMIT asm volatile("cp.async.commit_group;" ::: "memory")
#define CP_WAIT0  asm volatile("cp.async.wait_group 0;" ::: "memory")

// Scratch (static __device__ — no runtime allocation)
__device__ __align__(16) float g_U[TOTC * CH * DV];    // u               [64][128] row-major
__device__ __align__(16) float g_W[TOTC * CH * DK];    // kcd             [64][128] row-major
__device__ __align__(16) float g_ATT[TOTC * CH * CH];  // masked attn     [64][64]
__device__ __align__(16) float g_QG[TOTC * CH * DK];   // q*e^gcs         [64][128]
__device__ __align__(16) float g_KDT[TOTC * DK * CH];  // (k*e^{gl-g})^T  [128][64]
__device__ float g_EGL[TOTC];

// Phase-1 smem layout (floats)
#define P1_Q   0
#define P1_K   8448
#define P1_V   16896
#define P1_A   25344          // [64][68]
#define P1_VEC 29696          // 6 x 64
#define P1_SMEM ((30080) * 4)

// Phase-2 smem layout (floats)
#define SO_S   0              // S  swizzled col-major: 32 cols x 128      (4096)
#define SO_W   4096           // W  [64][132]                              (8448)
#define SO_P   12544          // qg [64][132]                              (8448)
#define SO_A   20992          // att [64][68]                              (4352)
#define SO_K   25344          // kdT [128][68]                             (8704)
#define SO_V   34048          // vnw swizzled col-major: 32 cols x 64      (2048)
#define P2_SMEM ((36096) * 4)

// ---------------------------------------------------------------------------
// Phase 1: per-chunk preprocessing. grid = 2048, block = 256. (unchanged)
// ---------------------------------------------------------------------------
__global__ __launch_bounds__(256, 1) void gdn_phase1(
    const float* __restrict__ qin, const float* __restrict__ kin,
    const float* __restrict__ vin, const float* __restrict__ gin,
    const float* __restrict__ bin)
{
    extern __shared__ float sm[];
    float* q_sh  = sm + P1_Q;        // [64][132]
    float* k_sh  = sm + P1_K;        // [64][132]
    float* v_sh  = sm + P1_V;        // [64][132]
    float* A_sh  = sm + P1_A;        // [64][68]
    float* gcs   = sm + P1_VEC;      // [64]
    float* betaS = gcs + 64;
    float* bgS   = betaS + 64;
    float* edec  = bgS + 64;
    float* egcs  = edec + 64;
    float* iegcs = egcs + 64;

    const int cid = blockIdx.x;
    const int n   = cid & (NC - 1);
    const int bh  = cid / NC;
    const int h   = bh & (NHEAD - 1);
    const int b   = bh / NHEAD;
    const int tid = threadIdx.x;
    const int s0  = n * CH;

    if (tid < CH) {
        int idx = (b * SEQ + s0 + tid) * NHEAD + h;
        gcs[tid]   = gin[idx];
        betaS[tid] = bin[idx];
    }
    __syncthreads();
    if (tid == 0) {
        float run = 0.f;
        #pragma unroll
        for (int i = 0; i < CH; i++) { run += gcs[i]; gcs[i] = run; }
    }
    __syncthreads();
    if (tid < CH) {
        float e  = __expf(gcs[tid]);
        egcs[tid]  = e;
        iegcs[tid] = 1.0f / e;
        bgS[tid]   = betaS[tid] * e;
    }
    __syncthreads();
    if (tid < CH) edec[tid] = egcs[CH - 1] * iegcs[tid];

    // Load + l2-normalize q and k (one warp per 8 rows)
    {
        const int w = tid >> 5, lane = tid & 31;
        #pragma unroll
        for (int r = 0; r < 8; r++) {
            const int i = w * 8 + r;
            const int base = ((b * SEQ + s0 + i) * NHEAD + h) * DK;
            float k0 = kin[base + lane],      k1 = kin[base + lane + 32];
            float k2 = kin[base + lane + 64], k3 = kin[base + lane + 96];
            float ss = k0*k0 + k1*k1 + k2*k2 + k3*k3;
            #pragma unroll
            for (int o = 16; o; o >>= 1) ss += __shfl_xor_sync(0xffffffffu, ss, o);
            float rn = rsqrtf(ss + 1e-6f);
            k_sh[i*132 + lane]      = k0 * rn; k_sh[i*132 + lane + 32] = k1 * rn;
            k_sh[i*132 + lane + 64] = k2 * rn; k_sh[i*132 + lane + 96] = k3 * rn;

            float q0 = qin[base + lane],      q1 = qin[base + lane + 32];
            float q2 = qin[base + lane + 64], q3 = qin[base + lane + 96];
            float sq = q0*q0 + q1*q1 + q2*q2 + q3*q3;
            #pragma unroll
            for (int o = 16; o; o >>= 1) sq += __shfl_xor_sync(0xffffffffu, sq, o);
            float rq = rsqrtf(sq + 1e-6f) * 0.08838834764831843f;
            q_sh[i*132 + lane]      = q0 * rq; q_sh[i*132 + lane + 32] = q1 * rq;
            q_sh[i*132 + lane + 64] = q2 * rq; q_sh[i*132 + lane + 96] = q3 * rq;
        }
    }
    // v * beta, vectorized
    {
        #pragma unroll
        for (int r = 0; r < 8; r++) {
            int e4 = tid + 256 * r;                // 0..2047
            int i = e4 >> 5, d4 = e4 & 31;
            float4 vv = *(const float4*)(vin + ((b * SEQ + s0 + i) * NHEAD + h) * DV + 4 * d4);
            float bb = betaS[i];
            vv.x *= bb; vv.y *= bb; vv.z *= bb; vv.w *= bb;
            *(float4*)&v_sh[i*132 + 4*d4] = vv;
        }
    }
    __syncthreads();

    // Full 64x64 GEMM (strided 4x4 tiles), packed over d (reduction dim)
    {
        const int ti = tid >> 4, tj = tid & 15;
        u64t ak[4][4], aq[4][4];
        #pragma unroll
        for (int a = 0; a < 4; a++)
            #pragma unroll
            for (int c = 0; c < 4; c++) { ak[a][c] = 0ull; aq[a][c] = 0ull; }

        for (int d = 0; d < DK; d += 4) {
            ulonglong2 kj[4], ki[4], qi[4];
            #pragma unroll
            for (int c = 0; c < 4; c++)
                kj[c] = *(const ulonglong2*)&k_sh[(tj + 16*c)*132 + d];
            #pragma unroll
            for (int a = 0; a < 4; a++) {
                ki[a] = *(const ulonglong2*)&k_sh[(ti + 16*a)*132 + d];
                qi[a] = *(const ulonglong2*)&q_sh[(ti + 16*a)*132 + d];
            }
            #pragma unroll
            for (int a = 0; a < 4; a++)
                #pragma unroll
                for (int c = 0; c < 4; c++) {
                    fmaA(ak[a][c], ki[a].x, kj[c].x);
                    fmaA(ak[a][c], ki[a].y, kj[c].y);
                    fmaA(aq[a][c], qi[a].x, kj[c].x);
                    fmaA(aq[a][c], qi[a].y, kj[c].y);
                }
        }
        float* dstA = g_ATT + cid * (CH * CH);
        float eg_i[4], be_i[4], ie_j[4];
        #pragma unroll
        for (int a = 0; a < 4; a++) {
            int i = ti + 16*a;
            eg_i[a] = egcs[i]; be_i[a] = betaS[i];
        }
        #pragma unroll
        for (int c = 0; c < 4; c++) {
            int j = tj + 16*c;
            ie_j[c] = iegcs[j];
        }
        #pragma unroll
        for (int a = 0; a < 4; a++) {
            int i = ti + 16*a;
            #pragma unroll
            for (int c = 0; c < 4; c++) {
                int j = tj + 16*c;
                float2 tk = up2(ak[a][c]);
                float2 tq = up2(aq[a][c]);
                float sk = tk.x + tk.y, sq = tq.x + tq.y;
                float dec = eg_i[a] * ie_j[c];
                A_sh[i*68 + j] = (i > j)  ? be_i[a] * dec * sk : 0.f;
                dstA[i*64 + j] = (i >= j) ? dec * sq           : 0.f;
            }
        }
    }
    __syncthreads();

    // Forward substitution (I + A) x = rhs; 256 columns (128 U + 128 W)
    {
        const int  col = tid & 127;
        const bool isU = tid < 128;
        float x[CH];
        #pragma unroll
        for (int i = 0; i < CH; i++) x[i] = 0.f;
        #pragma unroll
        for (int i = 0; i < CH; i++) {
            float acc = isU ? v_sh[i*132 + col] : k_sh[i*132 + col] * bgS[i];
            const int nb = (i + 3) >> 2;
            #pragma unroll
            for (int j4 = 0; j4 < nb; j4++) {
                float4 a4 = *(const float4*)&A_sh[i*68 + 4*j4];
                acc -= a4.x * x[4*j4] + a4.y * x[4*j4+1] + a4.z * x[4*j4+2] + a4.w * x[4*j4+3];
            }
            x[i] = acc;
        }
        float* dst = (isU ? g_U : g_W) + cid * (CH * DK) + col;
        #pragma unroll
        for (int i = 0; i < CH; i++) dst[i * 128] = x[i];
    }

    // qg = q * e^gcs (vectorized); kdT = (k * e^{glast-g})^T
    {
        #pragma unroll
        for (int r = 0; r < 8; r++) {
            int e4 = tid + 256 * r;
            int i = e4 >> 5, d4 = e4 & 31;
            float4 qq = *(const float4*)&q_sh[i*132 + 4*d4];
            float e = egcs[i];
            qq.x *= e; qq.y *= e; qq.z *= e; qq.w *= e;
            *(float4*)(g_QG + cid * (CH*DK) + e4 * 4) = qq;
        }
    }
    for (int e = tid; e < DK * CH; e += 256) {
        int d = e >> 6, i = e & 63;
        g_KDT[cid * (DK * CH) + e] = k_sh[i*132 + d] * edec[i];
    }
    if (tid == 0) g_EGL[cid] = egcs[CH - 1];
}

// ---------------------------------------------------------------------------
// Phase 2: sequential chunk scan. grid = 32 bh * 4 Dv-slices = 128 CTAs.
// f32x2 packed over the REDUCTION dim: no pk2 broadcast MOVs.
// S and v_new stored column-major with XOR swizzle (conflict-free).
// ---------------------------------------------------------------------------
__global__ __launch_bounds__(256, 1) void gdn_phase2(float* __restrict__ out)
{
    extern __shared__ float sm[];
    float* S_sh = sm + SO_S;     // swizzled col-major [32 c][128 k]
    float* bufW = sm + SO_W;     // [64][132]
    float* bufP = sm + SO_P;     // [64][132]
    float* attS = sm + SO_A;     // [64][68]
    float* kdS  = sm + SO_K;     // [128][68]
    float* vnwS = sm + SO_V;     // swizzled col-major [32 c][64 j]
    const unsigned sbase = (unsigned)__cvta_generic_to_shared(sm);

    const int bh    = blockIdx.x >> 2;
    const int slice = blockIdx.x & 3;
    const int h     = bh & (NHEAD - 1);
    const int b     = bh / NHEAD;
    const int tid   = threadIdx.x;
    const int tc    = tid & 7;           // column-group (4 cols each)
    const int tr    = tid >> 3;          // 0..31
    const int c0    = tc * 4;
    const int vb0   = slice * 32;
    const int tr3   = tr & 3;

    for (int e = tid; e < 4096; e += 256) S_sh[e] = 0.f;
    __syncthreads();

    for (int n = 0; n < NC; n++) {
        const int cid = bh * NC + n;
        const float* Wp = g_W   + cid * 8192;
        const float* Qp = g_QG  + cid * 8192;
        const float* Ap = g_ATT + cid * 4096;
        const float* Up = g_U   + cid * 8192;
        const float* Kp = g_KDT + cid * 8192;

        // stage W, P(=qg), att via cp.async
        #pragma unroll
        for (int r = 0; r < 8; r++) {
            int g = tid + 256 * r;               // 0..2047 float4s
            int i = g >> 5, d4 = g & 31;
            cpa16(sbase + (unsigned)((SO_W + i*132 + 4*d4) * 4), Wp + g * 4);
            cpa16(sbase + (unsigned)((SO_P + i*132 + 4*d4) * 4), Qp + g * 4);
        }
        #pragma unroll
        for (int r = 0; r < 4; r++) {
            int g = tid + 256 * r;               // 0..1023 float4s
            int i = g >> 4, j4 = g & 15;
            cpa16(sbase + (unsigned)((SO_A + i*68 + 4*j4) * 4), Ap + g * 4);
        }
        CP_COMMIT;

        // prefetch u rows + egl while cp.async lands
        const float4 u0v = *(const float4*)(Up + tr * 128 + vb0 + c0);
        const float4 u1v = *(const float4*)(Up + (tr + 32) * 128 + vb0 + c0);
        const float egl = g_EGL[cid];

        CP_WAIT0;
        __syncthreads();

        // loop1: vn = W@S, oa = qg@S — packed over k
        u64t vnA[2][4], oaA[2][4];
        #pragma unroll
        for (int m = 0; m < 2; m++)
            #pragma unroll
            for (int j = 0; j < 4; j++) { vnA[m][j] = 0ull; oaA[m][j] = 0ull; }

        const int w0row = tr * 132, w1row = (tr + 32) * 132;
        #pragma unroll 2
        for (int kk = 0; kk < 128; kk += 4) {
            int k4  = kk >> 2;
            int koff = (((k4 & ~7) | ((k4 ^ tc) & 7)) << 2);
            ulonglong2 w0 = *(const ulonglong2*)&bufW[w0row + kk];
            ulonglong2 w1 = *(const ulonglong2*)&bufW[w1row + kk];
            ulonglong2 p0 = *(const ulonglong2*)&bufP[w0row + kk];
            ulonglong2 p1 = *(const ulonglong2*)&bufP[w1row + kk];
            ulonglong2 s0 = *(const ulonglong2*)&S_sh[(c0+0)*128 + koff];
            ulonglong2 s1 = *(const ulonglong2*)&S_sh[(c0+1)*128 + koff];
            ulonglong2 s2 = *(const ulonglong2*)&S_sh[(c0+2)*128 + koff];
            ulonglong2 s3 = *(const ulonglong2*)&S_sh[(c0+3)*128 + koff];
            fmaA(vnA[0][0], w0.x, s0.x); fmaA(vnA[0][0], w0.y, s0.y);
            fmaA(vnA[0][1], w0.x, s1.x); fmaA(vnA[0][1], w0.y, s1.y);
            fmaA(vnA[0][2], w0.x, s2.x); fmaA(vnA[0][2], w0.y, s2.y);
            fmaA(vnA[0][3], w0.x, s3.x); fmaA(vnA[0][3], w0.y, s3.y);
            fmaA(vnA[1][0], w1.x, s0.x); fmaA(vnA[1][0], w1.y, s0.y);
            fmaA(vnA[1][1], w1.x, s1.x); fmaA(vnA[1][1], w1.y, s1.y);
            fmaA(vnA[1][2], w1.x, s2.x); fmaA(vnA[1][2], w1.y, s2.y);
            fmaA(vnA[1][3], w1.x, s3.x); fmaA(vnA[1][3], w1.y, s3.y);
            fmaA(oaA[0][0], p0.x, s0.x); fmaA(oaA[0][0], p0.y, s0.y);
            fmaA(oaA[0][1], p0.x, s1.x); fmaA(oaA[0][1], p0.y, s1.y);
            fmaA(oaA[0][2], p0.x, s2.x); fmaA(oaA[0][2], p0.y, s2.y);
            fmaA(oaA[0][3], p0.x, s3.x); fmaA(oaA[0][3], p0.y, s3.y);
            fmaA(oaA[1][0], p1.x, s0.x); fmaA(oaA[1][0], p1.y, s0.y);
            fmaA(oaA[1][1], p1.x, s1.x); fmaA(oaA[1][1], p1.y, s1.y);
            fmaA(oaA[1][2], p1.x, s2.x); fmaA(oaA[1][2], p1.y, s2.y);
            fmaA(oaA[1][3], p1.x, s3.x); fmaA(oaA[1][3], p1.y, s3.y);
        }
        // v_new = u - vn, store swizzled column-major
        #pragma unroll
        for (int m = 0; m < 2; m++) {
            const float4 uv = m ? u1v : u0v;
            const int i  = tr + 32 * m;
            const int i4 = i >> 2;
            const int ioff = (((i4 & ~7) | ((i4 ^ tc) & 7)) << 2) + tr3;
            float2 t0 = up2(vnA[m][0]), t1 = up2(vnA[m][1]);
            float2 t2 = up2(vnA[m][2]), t3 = up2(vnA[m][3]);
            vnwS[(c0+0)*64 + ioff] = uv.x - t0.x - t0.y;
            vnwS[(c0+1)*64 + ioff] = uv.y - t1.x - t1.y;
            vnwS[(c0+2)*64 + ioff] = uv.z - t2.x - t2.y;
            vnwS[(c0+3)*64 + ioff] = uv.w - t3.x - t3.y;
        }
        __syncthreads();

        // stage kdT now; its latency hides under loop2
        #pragma unroll
        for (int r = 0; r < 8; r++) {
            int g = tid + 256 * r;               // 0..2047 float4s
            int d = g >> 4, i4 = g & 15;
            cpa16(sbase + (unsigned)((SO_K + d*68 + 4*i4) * 4), Kp + g * 4);
        }
        CP_COMMIT;

        // loop2: oa += att @ v_new — packed over j
        const int a0row = tr * 68, a1row = (tr + 32) * 68;
        #pragma unroll 2
        for (int jg = 0; jg < 64; jg += 4) {
            int j4  = jg >> 2;
            int joff = (((j4 & ~7) | ((j4 ^ tc) & 7)) << 2);
            ulonglong2 a0 = *(const ulonglong2*)&attS[a0row + jg];
            ulonglong2 a1 = *(const ulonglong2*)&attS[a1row + jg];
            ulonglong2 v0 = *(const ulonglong2*)&vnwS[(c0+0)*64 + joff];
            ulonglong2 v1 = *(const ulonglong2*)&vnwS[(c0+1)*64 + joff];
            ulonglong2 v2 = *(const ulonglong2*)&vnwS[(c0+2)*64 + joff];
            ulonglong2 v3 = *(const ulonglong2*)&vnwS[(c0+3)*64 + joff];
            fmaA(oaA[0][0], a0.x, v0.x); fmaA(oaA[0][0], a0.y, v0.y);
            fmaA(oaA[0][1], a0.x, v1.x); fmaA(oaA[0][1], a0.y, v1.y);
            fmaA(oaA[0][2], a0.x, v2.x); fmaA(oaA[0][2], a0.y, v2.y);
            fmaA(oaA[0][3], a0.x, v3.x); fmaA(oaA[0][3], a0.y, v3.y);
            fmaA(oaA[1][0], a1.x, v0.x); fmaA(oaA[1][0], a1.y, v0.y);
            fmaA(oaA[1][1], a1.x, v1.x); fmaA(oaA[1][1], a1.y, v1.y);
            fmaA(oaA[1][2], a1.x, v2.x); fmaA(oaA[1][2], a1.y, v2.y);
            fmaA(oaA[1][3], a1.x, v3.x); fmaA(oaA[1][3], a1.y, v3.y);
        }
        // output
        #pragma unroll
        for (int m = 0; m < 2; m++) {
            float2 t0 = up2(oaA[m][0]), t1 = up2(oaA[m][1]);
            float2 t2 = up2(oaA[m][2]), t3 = up2(oaA[m][3]);
            float4 o;
            o.x = t0.x + t0.y; o.y = t1.x + t1.y;
            o.z = t2.x + t2.y; o.w = t3.x + t3.y;
            *(float4*)(out + ((b * SEQ + n * CH + tr + 32*m) * NHEAD + h) * DV + vb0 + c0) = o;
        }

        CP_WAIT0;
        __syncthreads();

        // loop3: S = S*egl + kdT @ v_new — packed over i2
        u64t sA[4][4];
        #pragma unroll
        for (int mm = 0; mm < 4; mm++)
            #pragma unroll
            for (int j = 0; j < 4; j++) sA[mm][j] = 0ull;

        #pragma unroll 2
        for (int i2 = 0; i2 < 64; i2 += 4) {
            int j4  = i2 >> 2;
            int joff = (((j4 & ~7) | ((j4 ^ tc) & 7)) << 2);
            ulonglong2 k0 = *(const ulonglong2*)&kdS[(tr      )*68 + i2];
            ulonglong2 k1 = *(const ulonglong2*)&kdS[(tr + 32 )*68 + i2];
            ulonglong2 k2 = *(const ulonglong2*)&kdS[(tr + 64 )*68 + i2];
            ulonglong2 k3 = *(const ulonglong2*)&kdS[(tr + 96 )*68 + i2];
            ulonglong2 v0 = *(const ulonglong2*)&vnwS[(c0+0)*64 + joff];
            ulonglong2 v1 = *(const ulonglong2*)&vnwS[(c0+1)*64 + joff];
            ulonglong2 v2 = *(const ulonglong2*)&vnwS[(c0+2)*64 + joff];
            ulonglong2 v3 = *(const ulonglong2*)&vnwS[(c0+3)*64 + joff];
            fmaA(sA[0][0], k0.x, v0.x); fmaA(sA[0][0], k0.y, v0.y);
            fmaA(sA[0][1], k0.x, v1.x); fmaA(sA[0][1], k0.y, v1.y);
            fmaA(sA[0][2], k0.x, v2.x); fmaA(sA[0][2], k0.y, v2.y);
            fmaA(sA[0][3], k0.x, v3.x); fmaA(sA[0][3], k0.y, v3.y);
            fmaA(sA[1][0], k1.x, v0.x); fmaA(sA[1][0], k1.y, v0.y);
            fmaA(sA[1][1], k1.x, v1.x); fmaA(sA[1][1], k1.y, v1.y);
            fmaA(sA[1][2], k1.x, v2.x); fmaA(sA[1][2], k1.y, v2.y);
            fmaA(sA[1][3], k1.x, v3.x); fmaA(sA[1][3], k1.y, v3.y);
            fmaA(sA[2][0], k2.x, v0.x); fmaA(sA[2][0], k2.y, v0.y);
            fmaA(sA[2][1], k2.x, v1.x); fmaA(sA[2][1], k2.y, v1.y);
            fmaA(sA[2][2], k2.x, v2.x); fmaA(sA[2][2], k2.y, v2.y);
            fmaA(sA[2][3], k2.x, v3.x); fmaA(sA[2][3], k2.y, v3.y);
            fmaA(sA[3][0], k3.x, v0.x); fmaA(sA[3][0], k3.y, v0.y);
            fmaA(sA[3][1], k3.x, v1.x); fmaA(sA[3][1], k3.y, v1.y);
            fmaA(sA[3][2], k3.x, v2.x); fmaA(sA[3][2], k3.y, v2.y);
            fmaA(sA[3][3], k3.x, v3.x); fmaA(sA[3][3], k3.y, v3.y);
        }
        // S update (scalar RMW, swizzled addresses, conflict-free)
        #pragma unroll
        for (int mm = 0; mm < 4; mm++) {
            const int k  = tr + 32 * mm;
            const int k4 = k >> 2;
            const int koff = (((k4 & ~7) | ((k4 ^ tc) & 7)) << 2) + tr3;
            float2 t0 = up2(sA[mm][0]), t1 = up2(sA[mm][1]);
            float2 t2 = up2(sA[mm][2]), t3 = up2(sA[mm][3]);
            float* p0 = &S_sh[(c0+0)*128 + koff];
            float* p1 = &S_sh[(c0+1)*128 + koff];
            float* p2 = &S_sh[(c0+2)*128 + koff];
            float* p3 = &S_sh[(c0+3)*128 + koff];
            *p0 = *p0 * egl + t0.x + t0.y;
            *p1 = *p1 * egl + t1.x + t1.y;
            *p2 = *p2 * egl + t2.x + t2.y;
            *p3 = *p3 * egl + t3.x + t3.y;
        }
        __syncthreads();
    }
}

// ---------------------------------------------------------------------------
extern "C" void kernel_launch(void* const* d_in, const int* in_sizes, int n_in,
                              void* d_out, int out_size) {
    (void)in_sizes; (void)n_in; (void)out_size;
    const float* q    = (const float*)d_in[0];
    const float* k    = (const float*)d_in[1];
    const float* v    = (const float*)d_in[2];
    const float* g    = (const float*)d_in[3];
    const float* beta = (const float*)d_in[4];
    float* out = (float*)d_out;

    cudaFuncSetAttribute(gdn_phase1, cudaFuncAttributeMaxDynamicSharedMemorySize, P1_SMEM);
    cudaFuncSetAttribute(gdn_phase2, cudaFuncAttributeMaxDynamicSharedMemorySize, P2_SMEM);

    gdn_phase1<<<TOTC, 256, P1_SMEM>>>(q, k, v, g, beta);
    gdn_phase2<<<NBATCH * NHEAD * 4, 256, P2_SMEM>>>(out);
}